// round 3
// baseline (speedup 1.0000x reference)
#include <cuda_runtime.h>
#include <math.h>

#define DD 256
#define NB 3072
#define KVSLOT 33280
#define NCHUNK 8

__device__ float g_dq[2*DD*NB];
__device__ float g_d3[2*DD*NB];
__device__ float g_dqold[2*DD*NB];
__device__ float g_qb[2*DD*NB];
__device__ float g_kb[2*DD*NB];
__device__ float g_vb[2*DD*NB];
__device__ float g_ob[2*DD*NB];
__device__ float g_msg[2*DD*NB];
__device__ float g_agg[2*DD*NB];
__device__ float g_tb[2*2*DD*NB];
__device__ float g_sc[2*NB*NB];
__device__ float g_kvpart[NCHUNK*KVSLOT];
__device__ float g_kvred[KVSLOT];
__device__ float g_wa[4*2*DD];
__device__ float g_rmax[2*NB];
__device__ float g_rsum[2*NB];
__device__ float g_cmax[2*NB];
__device__ float g_csum[2*NB];
__device__ int   g_i0[NB];
__device__ int   g_i1[NB];
__device__ int   g_valid0[NB];
__device__ float g_m0[NB];
__device__ float g_m1[NB];
__device__ float g_ms0buf[NB];

__device__ __forceinline__ unsigned f2tf(float x){
    unsigned r; asm("cvt.rna.tf32.f32 %0,%1;":"=r"(r):"f"(x)); return r;
}
__device__ __forceinline__ void mma8(float* c, const unsigned* a, const unsigned* b){
    asm volatile("mma.sync.aligned.m16n8k8.row.col.f32.tf32.tf32.f32 "
        "{%0,%1,%2,%3}, {%4,%5,%6,%7}, {%8,%9}, {%0,%1,%2,%3};"
        : "+f"(c[0]),"+f"(c[1]),"+f"(c[2]),"+f"(c[3])
        : "r"(a[0]),"r"(a[1]),"r"(a[2]),"r"(a[3]), "r"(b[0]),"r"(b[1]));
}

/* TF32x3 tensor-core GEMM.
   Out[z][o][j] = act(alpha*sum_c W(o,c)*X[z][c][j] + bias[o]) (+res)
   W(o,c) = wtrans ? W[c*O+o] : W[o*C+c]. Rows c<csplit from Xa else Xb.
   BM=128, BN=64, BK=16, 256 threads (8 warps, 4x2), warp tile 32x32. */
__global__ void __launch_bounds__(256) gemm_tc(
    const float* __restrict__ W, long long wz, int wtrans, int O,
    const float* __restrict__ Xa, long long xaz,
    const float* __restrict__ Xb, long long xbz, int csplit,
    const float* __restrict__ bias,
    const float* __restrict__ res, long long resz,
    float* __restrict__ Out, long long outz,
    int C, int N, float alpha, int act)
{
    __shared__ unsigned Ah[128][17], Al[128][17];
    __shared__ unsigned Bh[16][65],  Bl[16][65];
    const int z  = blockIdx.z;
    const int o0 = blockIdx.y * 128, j0 = blockIdx.x * 64;
    const float* Wp = W + (size_t)z * (size_t)wz;
    const int tid  = threadIdx.x;
    const int lane = tid & 31, w = tid >> 5;
    const int wm = w >> 1, wn = w & 1;
    const int g = lane >> 2, t = lane & 3;

    float acc[2][4][4];
    #pragma unroll
    for (int i=0;i<2;i++)
        #pragma unroll
        for (int j=0;j<4;j++)
            #pragma unroll
            for (int k=0;k<4;k++) acc[i][j][k]=0.f;

    for (int k0 = 0; k0 < C; k0 += 16) {
        /* load A tile: 128x16 */
        if (!wtrans) {
            #pragma unroll
            for (int it = 0; it < 8; it++) {
                int idx = tid + it*256;
                int o = idx >> 4, c = idx & 15;
                float v = Wp[(size_t)(o0+o)*C + k0 + c];
                unsigned h = f2tf(v);
                Ah[o][c] = h; Al[o][c] = f2tf(v - __uint_as_float(h));
            }
        } else {
            #pragma unroll
            for (int it = 0; it < 8; it++) {
                int idx = tid + it*256;
                int c = idx >> 7, o = idx & 127;
                float v = Wp[(size_t)(k0+c)*O + o0 + o];
                unsigned h = f2tf(v);
                Ah[o][c] = h; Al[o][c] = f2tf(v - __uint_as_float(h));
            }
        }
        /* load B tile: 16x64 */
        #pragma unroll
        for (int it = 0; it < 4; it++) {
            int idx = tid + it*256;
            int c = idx >> 6, n = idx & 63;
            int cg = k0 + c;
            const float* xp = (cg < csplit)
                ? Xa + (size_t)z*(size_t)xaz + (size_t)cg*N
                : Xb + (size_t)z*(size_t)xbz + (size_t)(cg-csplit)*N;
            float v = xp[j0 + n];
            unsigned h = f2tf(v);
            Bh[c][n] = h; Bl[c][n] = f2tf(v - __uint_as_float(h));
        }
        __syncthreads();
        #pragma unroll
        for (int kk = 0; kk < 16; kk += 8) {
            unsigned ah[2][4], al[2][4], bh[4][2], bl[4][2];
            #pragma unroll
            for (int mt = 0; mt < 2; mt++) {
                int r0 = wm*32 + mt*16 + g;
                ah[mt][0]=Ah[r0][kk+t];   al[mt][0]=Al[r0][kk+t];
                ah[mt][1]=Ah[r0+8][kk+t]; al[mt][1]=Al[r0+8][kk+t];
                ah[mt][2]=Ah[r0][kk+t+4]; al[mt][2]=Al[r0][kk+t+4];
                ah[mt][3]=Ah[r0+8][kk+t+4];al[mt][3]=Al[r0+8][kk+t+4];
            }
            #pragma unroll
            for (int nt = 0; nt < 4; nt++) {
                int cc = wn*32 + nt*8 + g;
                bh[nt][0]=Bh[kk+t][cc];   bl[nt][0]=Bl[kk+t][cc];
                bh[nt][1]=Bh[kk+t+4][cc]; bl[nt][1]=Bl[kk+t+4][cc];
            }
            #pragma unroll
            for (int mt = 0; mt < 2; mt++)
                #pragma unroll
                for (int nt = 0; nt < 4; nt++) {
                    mma8(acc[mt][nt], ah[mt], bh[nt]);
                    mma8(acc[mt][nt], ah[mt], bl[nt]);
                    mma8(acc[mt][nt], al[mt], bh[nt]);
                }
        }
        __syncthreads();
    }
    /* epilogue */
    #pragma unroll
    for (int mt = 0; mt < 2; mt++) {
        #pragma unroll
        for (int nt = 0; nt < 4; nt++) {
            int row0 = o0 + wm*32 + mt*16 + g;
            int col0 = j0 + wn*32 + nt*8 + 2*t;
            #pragma unroll
            for (int e = 0; e < 4; e++) {
                int o  = row0 + (e >> 1)*8;
                int jj = col0 + (e & 1);
                float v = acc[mt][nt][e]*alpha + (bias ? bias[o] : 0.f);
                if (act == 2) v = v > 0.f ? v : (__expf(v) - 1.f);
                if (res) v += res[(size_t)z*(size_t)resz + (size_t)o*N + jj];
                Out[(size_t)z*(size_t)outz + (size_t)o*N + jj] = v;
            }
        }
    }
}

/* linear attention stage 1: partial KV[64][64] & ksum[64] per (chunk,h,b) */
__global__ void __launch_bounds__(256) attn_kv_kernel(
    const float* __restrict__ K, const float* __restrict__ V,
    float* __restrict__ part, int ns)
{
    int chunk = blockIdx.x, h = blockIdx.y, b = blockIdx.z;
    int mlen = ns / NCHUNK, m0 = chunk * mlen;
    const float* Kb = K + (size_t)b*DD*ns;
    const float* Vb = V + (size_t)b*DD*ns;
    __shared__ float ks[64][33];
    __shared__ float vs[64][33];
    int tid = threadIdx.x;
    int qi0 = (tid>>4)*4, ki0 = (tid&15)*4;
    float acc[4][4]={{0,0,0,0},{0,0,0,0},{0,0,0,0},{0,0,0,0}};
    float ksum = 0.f, invm = 1.f/(float)ns;
    for (int mt = 0; mt < mlen; mt += 32) {
        __syncthreads();
        for (int idx = tid; idx < 64*32; idx += 256) {
            int d = idx>>5, mm = idx&31, m = m0+mt+mm;
            float kr = Kb[(size_t)(d*4+h)*ns + m];
            ks[d][mm] = kr>0.f ? kr+1.f : __expf(kr);
            vs[d][mm] = Vb[(size_t)(d*4+h)*ns + m]*invm;
        }
        __syncthreads();
        if (tid < 64) {
            #pragma unroll
            for (int mm=0;mm<32;mm++) ksum += ks[tid][mm];
        }
        #pragma unroll 4
        for (int mm=0;mm<32;mm++){
            float vv[4], kv[4];
            #pragma unroll
            for (int i=0;i<4;i++) vv[i]=vs[qi0+i][mm];
            #pragma unroll
            for (int j=0;j<4;j++) kv[j]=ks[ki0+j][mm];
            #pragma unroll
            for (int i=0;i<4;i++)
                #pragma unroll
                for (int j=0;j<4;j++) acc[i][j]+=vv[i]*kv[j];
        }
    }
    float* dst = part + (size_t)chunk*KVSLOT;
    size_t base = (size_t)(b*4+h)*64;
    #pragma unroll
    for (int i=0;i<4;i++)
        #pragma unroll
        for (int j=0;j<4;j++)
            dst[(base+qi0+i)*64 + ki0+j] = acc[i][j];
    if (tid < 64) dst[32768 + base + tid] = ksum;
}

__global__ void kv_reduce_kernel(const float* __restrict__ part, float* __restrict__ o)
{
    int i = blockIdx.x*256 + threadIdx.x;
    if (i < KVSLOT) {
        float s = 0.f;
        #pragma unroll
        for (int c=0;c<NCHUNK;c++) s += part[(size_t)c*KVSLOT + i];
        o[i] = s;
    }
}

__global__ void __launch_bounds__(128) attn_out_kernel(
    const float* __restrict__ Q, const float* __restrict__ KVr,
    float* __restrict__ O_, int nq, int ns)
{
    int b = blockIdx.z, h = blockIdx.y;
    int m = blockIdx.x*128 + threadIdx.x;
    __shared__ float kvs[64][64];
    __shared__ float kss[64];
    const float* src = KVr + (size_t)(b*4+h)*4096;
    for (int i = threadIdx.x; i < 4096; i += 128) kvs[i>>6][i&63] = src[i];
    if (threadIdx.x < 64) kss[threadIdx.x] = KVr[32768 + (size_t)(b*4+h)*64 + threadIdx.x];
    __syncthreads();
    const float* Qb = Q + (size_t)b*DD*nq;
    float qv[64], denom = 0.f;
    #pragma unroll
    for (int d=0;d<64;d++){
        float q = Qb[(size_t)(d*4+h)*nq + m];
        q = q>0.f ? q+1.f : __expf(q);
        qv[d]=q; denom += q*kss[d];
    }
    float zf = (float)ns/(denom + 1e-6f);
    float* Ob = O_ + (size_t)b*DD*nq;
    for (int qd=0; qd<64; qd++){
        float accv = 0.f;
        #pragma unroll
        for (int d=0;d<64;d++) accv += qv[d]*kvs[qd][d];
        Ob[(size_t)(qd*4+h)*nq + m] = accv*zf;
    }
}

__global__ void __launch_bounds__(256) instnorm_relu_kernel(float* X, int C, int n)
{
    int c = blockIdx.x, b = blockIdx.y;
    float* row = X + ((size_t)b*C + c)*n;
    int tid = threadIdx.x;
    float s=0.f, s2=0.f;
    for (int i=tid;i<n;i+=256){ float v=row[i]; s+=v; s2+=v*v; }
    __shared__ float sm1[256], sm2[256];
    sm1[tid]=s; sm2[tid]=s2; __syncthreads();
    for (int st=128;st;st>>=1){
        if (tid<st){ sm1[tid]+=sm1[tid+st]; sm2[tid]+=sm2[tid+st]; }
        __syncthreads();
    }
    float mean = sm1[0]/(float)n;
    float var = sm2[0]/(float)n - mean*mean;
    float rstd = rsqrtf(var + 1e-5f);
    for (int i=tid;i<n;i+=256){
        float v = (row[i]-mean)*rstd;
        row[i] = v>0.f ? v : 0.f;
    }
}

__global__ void gat_vec_kernel(const float* __restrict__ gatW,
                               const float* __restrict__ gata, float* __restrict__ wa)
{
    int gg = blockIdx.x, d = threadIdx.x;
    const float* W = gatW + (size_t)gg*DD*DD;
    const float* a = gata + (size_t)gg*2*DD;
    float s1=0.f, s2=0.f;
    for (int o=0;o<DD;o++){ float w=W[(size_t)d*DD+o]; s1+=w*a[o]; s2+=w*a[DD+o]; }
    wa[gg*2*DD + d] = s1;
    wa[gg*2*DD + DD + d] = s2;
}

__global__ void __launch_bounds__(256) gat_agg_kernel(
    const float* __restrict__ d3, const float* __restrict__ d2d,
    const float* __restrict__ wa, float* __restrict__ agg, int n)
{
    int b = blockIdx.y;
    int warp = threadIdx.x>>5, lane = threadIdx.x&31;
    int nn = blockIdx.x*8 + warp;
    const float* Wa1 = wa;
    const float* Wa2 = wa + DD;
    const float* d3b = d3 + (size_t)b*DD*n;
    const float* d2b = d2d + (size_t)b*DD*(size_t)n*8;
    size_t n8 = (size_t)n*8;
    float x3[8], w2v[8];
    float sself=0.f, s0=0.f;
    #pragma unroll
    for (int r=0;r<8;r++){
        int d = lane + r*32;
        x3[r]=d3b[(size_t)d*n+nn]; w2v[r]=Wa2[d];
        sself += x3[r]*Wa1[d]; s0 += x3[r]*w2v[r];
    }
    #pragma unroll
    for (int off=16;off;off>>=1){
        sself += __shfl_xor_sync(0xffffffffu, sself, off);
        s0    += __shfl_xor_sync(0xffffffffu, s0, off);
    }
    float e[9]; e[0] = sself + s0;
    size_t nbase = (size_t)nn*8;
    #pragma unroll
    for (int l=1;l<9;l++){
        float sl = 0.f;
        #pragma unroll
        for (int r=0;r<8;r++)
            sl += d2b[(size_t)(lane+r*32)*n8 + nbase + (l-1)] * w2v[r];
        #pragma unroll
        for (int off=16;off;off>>=1) sl += __shfl_xor_sync(0xffffffffu, sl, off);
        e[l] = sself + sl;
    }
    float mx = -1e30f;
    #pragma unroll
    for (int l=0;l<9;l++){ e[l] = e[l]>0.f ? e[l] : 0.2f*e[l]; mx = fmaxf(mx, e[l]); }
    float sum = 0.f;
    #pragma unroll
    for (int l=0;l<9;l++){ e[l] = __expf(e[l]-mx); sum += e[l]; }
    float inv = 1.f/sum;
    float accv[8];
    #pragma unroll
    for (int r=0;r<8;r++) accv[r] = e[0]*inv*x3[r];
    #pragma unroll
    for (int l=1;l<9;l++){
        float al = e[l]*inv;
        #pragma unroll
        for (int r=0;r<8;r++)
            accv[r] += al * d2b[(size_t)(lane+r*32)*n8 + nbase + (l-1)];
    }
    float* ab = agg + (size_t)b*DD*n;
    #pragma unroll
    for (int r=0;r<8;r++) ab[(size_t)(lane+r*32)*n + nn] = accv[r];
}

__global__ void colnorm_kernel(float* X, int n)
{
    int b = blockIdx.y;
    int col = blockIdx.x*256 + threadIdx.x;
    float* Xb = X + (size_t)b*DD*n;
    float s = 0.f;
    for (int d=0;d<DD;d++){ float v=Xb[(size_t)d*n+col]; s += v*v; }
    float inv = 1.f / fmaxf(sqrtf(s), 1e-12f);
    for (int d=0;d<DD;d++) Xb[(size_t)d*n+col] *= inv;
}

__global__ void __launch_bounds__(256) row_stats_kernel(
    const float* __restrict__ S, float* rmax, float* rsum, int n1, int n2)
{
    int br = blockIdx.y*n1 + blockIdx.x;
    const float* row = S + (size_t)br*n2;
    int tid = threadIdx.x;
    __shared__ float sm[256];
    float mx = -1e30f;
    for (int j=tid;j<n2;j+=256) mx = fmaxf(mx, row[j]);
    sm[tid]=mx; __syncthreads();
    for (int st=128;st;st>>=1){ if (tid<st) sm[tid]=fmaxf(sm[tid],sm[tid+st]); __syncthreads(); }
    mx = sm[0]; __syncthreads();
    float s = 0.f;
    for (int j=tid;j<n2;j+=256) s += __expf(row[j]-mx);
    sm[tid]=s; __syncthreads();
    for (int st=128;st;st>>=1){ if (tid<st) sm[tid]+=sm[tid+st]; __syncthreads(); }
    if (tid==0){ rmax[br]=mx; rsum[br]=sm[0]; }
}

__global__ void col_stats_kernel(const float* __restrict__ S,
                                 float* cmax, float* csum, int n1, int n2)
{
    int b = blockIdx.y;
    int c = blockIdx.x*256 + threadIdx.x;
    const float* Sb = S + (size_t)b*n1*n2;
    float mx = -1e30f, s = 0.f;
    for (int r=0;r<n1;r++){
        float v = Sb[(size_t)r*n2 + c];
        if (v > mx){ s = s*__expf(mx-v) + 1.f; mx = v; }
        else s += __expf(v-mx);
    }
    cmax[b*n1 + c] = mx;
    csum[b*n1 + c] = s;
}

__global__ void conf_kernel(const float* __restrict__ S,
    const float* __restrict__ rmax, const float* __restrict__ rsum,
    const float* __restrict__ cmax, const float* __restrict__ csum,
    float* __restrict__ conf)
{
    size_t idx = (size_t)blockIdx.x*256 + threadIdx.x;
    int z = (int)(idx / ((size_t)NB*NB));
    size_t rem = idx - (size_t)z*NB*NB;
    int n = (int)(rem / NB), m = (int)(rem % NB);
    float s = S[idx];
    conf[idx] = __expf(2.f*s - rmax[z*NB+n] - cmax[z*NB+m])
                / (rsum[z*NB+n]*csum[z*NB+m]);
}

__global__ void __launch_bounds__(256) rowargmax_kernel(
    const float* __restrict__ conf0, int* i0, float* m0)
{
    int n = blockIdx.x;
    const float* row = conf0 + (size_t)n*NB;
    int tid = threadIdx.x;
    float best = -1e30f; int bidx = 0;
    for (int m=tid;m<NB;m+=256){ float v=row[m]; if (v>best){best=v;bidx=m;} }
    __shared__ float bv[256]; __shared__ int bi[256];
    bv[tid]=best; bi[tid]=bidx; __syncthreads();
    for (int st=128;st;st>>=1){
        if (tid<st){
            if (bv[tid+st]>bv[tid] || (bv[tid+st]==bv[tid] && bi[tid+st]<bi[tid])){
                bv[tid]=bv[tid+st]; bi[tid]=bi[tid+st];
            }
        }
        __syncthreads();
    }
    if (tid==0){ i0[n]=bi[0]; m0[n]=bv[0]; }
}

__global__ void colargmax_kernel(const float* __restrict__ conf0, int* i1, float* m1)
{
    int m = blockIdx.x*256 + threadIdx.x;
    float best = -1e30f; int bidx = 0;
    for (int n=0;n<NB;n++){
        float v = conf0[(size_t)n*NB + m];
        if (v > best){ best=v; bidx=n; }
    }
    i1[m]=bidx; m1[m]=best;
}

__global__ void match0_kernel(const int* i0, const int* i1, const float* m0,
                              float* out, float* ms0buf, int* valid0)
{
    int n = blockIdx.x*256 + threadIdx.x;
    int t = i0[n];
    int mutual = (i1[t] == n);
    float ms0 = mutual ? m0[n] : 0.f;
    int v0 = mutual && (ms0 > 0.2f);
    out[n] = v0 ? (float)t : -1.f;
    out[2*NB + n] = ms0;
    ms0buf[n] = ms0;
    valid0[n] = v0;
}

__global__ void match1_kernel(const int* i0, const int* i1,
                              const float* ms0buf, const int* valid0, float* out)
{
    int m = blockIdx.x*256 + threadIdx.x;
    int t = i1[m];
    int mutual = (i0[t] == m);
    float ms1 = mutual ? ms0buf[t] : 0.f;
    int v1 = mutual && valid0[t];
    out[NB + m] = v1 ? (float)t : -1.f;
    out[3*NB + m] = ms1;
}

/* --------------------------------- host ---------------------------------- */
static void* gsym(const void* s){ void* p=nullptr; cudaGetSymbolAddress(&p, s); return p; }

struct Ptrs {
    float *dq,*d3,*dqold,*qb,*kb,*vb,*ob,*msg,*agg,*tb,*sc,*kvpart,*kvred,*wa;
    float *rmax,*rsum,*cmax,*csum,*m0,*m1,*ms0buf;
    int *i0,*i1,*valid0;
};

static void ap(float* x, const float* src, int ai,
               const float* projw, const float* projb,
               const float* mergew, const float* mergeb,
               const float* mlp1w, const float* mlp1b,
               const float* mlp2w, const float* mlp2b, const Ptrs& P)
{
    const int N = NB;
    const long long DN = (long long)DD*N;
    dim3 g2(N/64, 2, 2), g4(N/64, 4, 2);
    const float* pw = projw + (size_t)ai*3*DD*DD;
    const float* pb = projb + (size_t)ai*3*DD;
    gemm_tc<<<g2,256>>>(pw,         0,0,DD, x,  DN, x,  DN, DD, pb,      nullptr,0, P.qb, DN, DD, N, 1.f, 0);
    gemm_tc<<<g2,256>>>(pw+DD*DD,   0,0,DD, src,DN, src,DN, DD, pb+DD,   nullptr,0, P.kb, DN, DD, N, 1.f, 0);
    gemm_tc<<<g2,256>>>(pw+2*DD*DD, 0,0,DD, src,DN, src,DN, DD, pb+2*DD, nullptr,0, P.vb, DN, DD, N, 1.f, 0);
    attn_kv_kernel<<<dim3(NCHUNK,4,2),256>>>(P.kb, P.vb, P.kvpart, N);
    kv_reduce_kernel<<<KVSLOT/256,256>>>(P.kvpart, P.kvred);
    attn_out_kernel<<<dim3(N/128,4,2),128>>>(P.qb, P.kvred, P.ob, N, N);
    gemm_tc<<<g2,256>>>(mergew+(size_t)ai*DD*DD, 0,0,DD, P.ob,DN, P.ob,DN, DD,
                        mergeb+(size_t)ai*DD, nullptr,0, P.msg, DN, DD, N, 1.f, 0);
    gemm_tc<<<g4,256>>>(mlp1w+(size_t)ai*512*512, 0,0,512, x,DN, P.msg,DN, DD,
                        mlp1b+(size_t)ai*512, nullptr,0, P.tb, 512LL*N, 512, N, 1.f, 0);
    instnorm_relu_kernel<<<dim3(512,2),256>>>(P.tb, 512, N);
    gemm_tc<<<g2,256>>>(mlp2w+(size_t)ai*DD*512, 0,0,DD, P.tb,512LL*N, P.tb,512LL*N, 512,
                        mlp2b+(size_t)ai*DD, x, DN, x, DN, 512, N, 1.f, 0);
}

extern "C" void kernel_launch(void* const* d_in, const int* in_sizes, int n_in,
                              void* d_out, int out_size)
{
    const float* in_dq   = (const float*)d_in[0];
    const float* in_d3   = (const float*)d_in[1];
    const float* in_d2db = (const float*)d_in[2];
    const float* projw   = (const float*)d_in[3];
    const float* projb   = (const float*)d_in[4];
    const float* mergew  = (const float*)d_in[5];
    const float* mergeb  = (const float*)d_in[6];
    const float* mlp1w   = (const float*)d_in[7];
    const float* mlp1b   = (const float*)d_in[8];
    const float* mlp2w   = (const float*)d_in[9];
    const float* mlp2b   = (const float*)d_in[10];
    const float* gatW    = (const float*)d_in[11];
    const float* gata    = (const float*)d_in[12];
    const float* finw    = (const float*)d_in[13];
    const float* finb    = (const float*)d_in[14];
    float* out = (float*)d_out;

    Ptrs P;
    P.dq=(float*)gsym(g_dq); P.d3=(float*)gsym(g_d3); P.dqold=(float*)gsym(g_dqold);
    P.qb=(float*)gsym(g_qb); P.kb=(float*)gsym(g_kb); P.vb=(float*)gsym(g_vb);
    P.ob=(float*)gsym(g_ob); P.msg=(float*)gsym(g_msg); P.agg=(float*)gsym(g_agg);
    P.tb=(float*)gsym(g_tb); P.sc=(float*)gsym(g_sc);
    P.kvpart=(float*)gsym(g_kvpart); P.kvred=(float*)gsym(g_kvred); P.wa=(float*)gsym(g_wa);
    P.rmax=(float*)gsym(g_rmax); P.rsum=(float*)gsym(g_rsum);
    P.cmax=(float*)gsym(g_cmax); P.csum=(float*)gsym(g_csum);
    P.m0=(float*)gsym(g_m0); P.m1=(float*)gsym(g_m1); P.ms0buf=(float*)gsym(g_ms0buf);
    P.i0=(int*)gsym(g_i0); P.i1=(int*)gsym(g_i1); P.valid0=(int*)gsym(g_valid0);

    const int N = NB;
    const long long DN = (long long)DD*N;
    size_t bytes = (size_t)2*DD*N*sizeof(float);
    cudaMemcpyAsync(P.dq, in_dq, bytes, cudaMemcpyDeviceToDevice);
    cudaMemcpyAsync(P.d3, in_d3, bytes, cudaMemcpyDeviceToDevice);
    gat_vec_kernel<<<4,256>>>(gatW, gata, P.wa);

    int gi = 0, ai = 0;
    for (int step = 0; step < 12; step++) {
        int t = step % 3;
        if (t == 0) {
            gat_agg_kernel<<<dim3(N/8,2),256>>>(P.d3, in_d2db, P.wa + gi*2*DD, P.agg, N);
            gemm_tc<<<dim3(N/64,2,2),256>>>(gatW+(size_t)gi*DD*DD, 0,1,DD,
                P.agg,DN, P.agg,DN, DD, nullptr, nullptr,0, P.d3, DN, DD, N, 1.f, 2);
            gi++;
        } else if (t == 1) {
            ap(P.dq, P.dq, ai, projw,projb,mergew,mergeb,mlp1w,mlp1b,mlp2w,mlp2b, P);
            ap(P.d3, P.d3, ai, projw,projb,mergew,mergeb,mlp1w,mlp1b,mlp2w,mlp2b, P);
            ai++;
        } else {
            cudaMemcpyAsync(P.dqold, P.dq, bytes, cudaMemcpyDeviceToDevice);
            ap(P.dq, P.d3,    ai, projw,projb,mergew,mergeb,mlp1w,mlp1b,mlp2w,mlp2b, P);
            ap(P.d3, P.dqold, ai, projw,projb,mergew,mergeb,mlp1w,mlp1b,mlp2w,mlp2b, P);
            ai++;
        }
    }

    gemm_tc<<<dim3(N/64,2,2),256>>>(finw, 0,0,DD, P.dq,DN, P.dq,DN, DD, finb,
                                    nullptr,0, P.qb, DN, DD, N, 1.f, 0);
    gemm_tc<<<dim3(N/64,2,2),256>>>(finw, 0,0,DD, P.d3,DN, P.d3,DN, DD, finb,
                                    nullptr,0, P.kb, DN, DD, N, 1.f, 0);
    colnorm_kernel<<<dim3(N/256,2),256>>>(P.qb, N);
    colnorm_kernel<<<dim3(N/256,2),256>>>(P.kb, N);

    /* scores: [b, n1, n2] = mq^T md / 0.1 */
    gemm_tc<<<dim3(N/64,N/128,2),256>>>(P.qb, DN, 1, N, P.kb, DN, P.kb, DN, DD,
                                        nullptr, nullptr,0, P.sc, (long long)N*N,
                                        DD, N, 10.f, 0);
    row_stats_kernel<<<dim3(N,2),256>>>(P.sc, P.rmax, P.rsum, N, N);
    col_stats_kernel<<<dim3(N/256,2),256>>>(P.sc, P.cmax, P.csum, N, N);

    float* conf = out + 4*NB;
    conf_kernel<<<(unsigned)((size_t)2*N*N/256),256>>>(P.sc, P.rmax, P.rsum,
                                                       P.cmax, P.csum, conf);
    rowargmax_kernel<<<N,256>>>(conf, P.i0, P.m0);
    colargmax_kernel<<<N/256,256>>>(conf, P.i1, P.m1);
    match0_kernel<<<N/256,256>>>(P.i0, P.i1, P.m0, out, P.ms0buf, P.valid0);
    match1_kernel<<<N/256,256>>>(P.i0, P.i1, P.ms0buf, P.valid0, out);
}

// round 4
// speedup vs baseline: 1.8380x; 1.8380x over previous
#include <cuda_runtime.h>
#include <cuda_bf16.h>
#include <math.h>

#define DD 256
#define NB 3072
#define KVSLOT 33280
#define NCHUNK 8

__device__ float g_dq[2*DD*NB];
__device__ float g_d3[2*DD*NB];
__device__ float g_dqold[2*DD*NB];
__device__ float g_qb[2*DD*NB];
__device__ float g_kb[2*DD*NB];
__device__ float g_vb[2*DD*NB];
__device__ float g_ob[2*DD*NB];
__device__ float g_msg[2*DD*NB];
__device__ float g_agg[2*DD*NB];
__device__ float g_tb[2*2*DD*NB];
__device__ float g_sc[2*NB*NB];
__device__ float g_kvpart[NCHUNK*KVSLOT];
__device__ float g_kvred[KVSLOT];
__device__ float g_wa[4*2*DD];
__device__ float g_rmax[2*NB];
__device__ float g_rsum[2*NB];
__device__ float g_cmax[2*NB];
__device__ float g_csum[2*NB];
__device__ int   g_i0[NB];
__device__ int   g_i1[NB];
__device__ int   g_valid0[NB];
__device__ float g_m0[NB];
__device__ float g_m1[NB];
__device__ float g_ms0buf[NB];

/* pack two floats to bf16x2 word: low half = first arg */
__device__ __forceinline__ unsigned packbf(float lo, float hi){
    unsigned r; asm("cvt.rn.bf16x2.f32 %0,%1,%2;":"=r"(r):"f"(hi),"f"(lo)); return r;
}
__device__ __forceinline__ unsigned short bf1(float v){
    __nv_bfloat16 b = __float2bfloat16(v);
    return *reinterpret_cast<unsigned short*>(&b);
}
__device__ __forceinline__ float bf2f(unsigned short u){
    return __uint_as_float(((unsigned)u) << 16);
}
__device__ __forceinline__ void mma16(float* c, const unsigned* a, const unsigned* b){
    asm volatile("mma.sync.aligned.m16n8k16.row.col.f32.bf16.bf16.f32 "
        "{%0,%1,%2,%3}, {%4,%5,%6,%7}, {%8,%9}, {%0,%1,%2,%3};"
        : "+f"(c[0]),"+f"(c[1]),"+f"(c[2]),"+f"(c[3])
        : "r"(a[0]),"r"(a[1]),"r"(a[2]),"r"(a[3]), "r"(b[0]),"r"(b[1]));
}

/* BF16x3 tensor-core GEMM.
   Out[z][o][j] = act(alpha*sum_c W(o,c)*X[z][c][j] + bias[o]) (+res)
   W(o,c) = wtrans ? W[c*O+o] : W[o*C+c]. Rows c<csplit from Xa else Xb.
   BM=64, BN=64, BK=32, 128 threads (4 warps 2x2), warp tile 32x32. */
__global__ void __launch_bounds__(128) gemm_tc(
    const float* __restrict__ W, long long wz, int wtrans, int O,
    const float* __restrict__ Xa, long long xaz,
    const float* __restrict__ Xb, long long xbz, int csplit,
    const float* __restrict__ bias,
    const float* __restrict__ res, long long resz,
    float* __restrict__ Out, long long outz,
    int C, int N, float alpha, int act)
{
    __shared__ unsigned sAh[64][17], sAl[64][17];   /* [row][kpair] */
    __shared__ unsigned sBh[16][69], sBl[16][69];   /* [kpair][col] */
    const int z  = blockIdx.z;
    const int o0 = blockIdx.y * 64, j0 = blockIdx.x * 64;
    const float* Wp = W + (size_t)z * (size_t)wz;
    const float* Xaz = Xa + (size_t)z * (size_t)xaz;
    const float* Xbz = Xb + (size_t)z * (size_t)xbz;
    const int tid  = threadIdx.x;
    const int lane = tid & 31, w = tid >> 5;
    const int wm = w >> 1, wn = w & 1;
    const int g = lane >> 2, t = lane & 3;

    float acc[2][4][4];
    #pragma unroll
    for (int i=0;i<2;i++)
        #pragma unroll
        for (int j=0;j<4;j++)
            #pragma unroll
            for (int k=0;k<4;k++) acc[i][j][k]=0.f;

    float2 apre2[8];   /* !wtrans prefetch: 8 kpairs */
    float  apre1[16];  /* wtrans prefetch */
    float  bpre[16];

    /* prefetch tile 0 */
    if (!wtrans) {
        #pragma unroll
        for (int i = 0; i < 8; i++) {
            int idx = tid + i*128;
            int o = idx >> 4, p = idx & 15;
            apre2[i] = *(const float2*)(Wp + (size_t)(o0+o)*C + 2*p);
        }
    } else {
        #pragma unroll
        for (int i = 0; i < 16; i++) {
            int idx = tid + i*128;
            int o = idx & 63, c = idx >> 6;
            apre1[i] = Wp[(size_t)c*O + o0 + o];
        }
    }
    #pragma unroll
    for (int i = 0; i < 16; i++) {
        int idx = tid + i*128;
        int c = idx >> 6, n = idx & 63;
        const float* xp = (c < csplit) ? Xaz + (size_t)c*N
                                       : Xbz + (size_t)(c-csplit)*N;
        bpre[i] = xp[j0 + n];
    }

    const int ntiles = C >> 5;
    for (int kt = 0; kt < ntiles; kt++) {
        __syncthreads();
        /* store prefetched tile to smem with bf16 hi/lo split */
        if (!wtrans) {
            #pragma unroll
            for (int i = 0; i < 8; i++) {
                int idx = tid + i*128;
                int o = idx >> 4, p = idx & 15;
                float2 v = apre2[i];
                unsigned hw = packbf(v.x, v.y);
                float h0 = __uint_as_float(hw << 16);
                float h1 = __uint_as_float(hw & 0xffff0000u);
                sAh[o][p] = hw;
                sAl[o][p] = packbf(v.x - h0, v.y - h1);
            }
        } else {
            #pragma unroll
            for (int i = 0; i < 16; i++) {
                int idx = tid + i*128;
                int o = idx & 63, c = idx >> 6;
                float v = apre1[i];
                unsigned short hb = bf1(v);
                ((unsigned short*)sAh)[(o*17 + (c>>1))*2 + (c&1)] = hb;
                ((unsigned short*)sAl)[(o*17 + (c>>1))*2 + (c&1)] = bf1(v - bf2f(hb));
            }
        }
        #pragma unroll
        for (int i = 0; i < 16; i++) {
            int idx = tid + i*128;
            int c = idx >> 6, n = idx & 63;
            float v = bpre[i];
            unsigned short hb = bf1(v);
            ((unsigned short*)sBh)[((c>>1)*69 + n)*2 + (c&1)] = hb;
            ((unsigned short*)sBl)[((c>>1)*69 + n)*2 + (c&1)] = bf1(v - bf2f(hb));
        }
        __syncthreads();
        /* prefetch next tile */
        if (kt + 1 < ntiles) {
            int k0 = (kt + 1) << 5;
            if (!wtrans) {
                #pragma unroll
                for (int i = 0; i < 8; i++) {
                    int idx = tid + i*128;
                    int o = idx >> 4, p = idx & 15;
                    apre2[i] = *(const float2*)(Wp + (size_t)(o0+o)*C + k0 + 2*p);
                }
            } else {
                #pragma unroll
                for (int i = 0; i < 16; i++) {
                    int idx = tid + i*128;
                    int o = idx & 63, c = idx >> 6;
                    apre1[i] = Wp[(size_t)(k0+c)*O + o0 + o];
                }
            }
            #pragma unroll
            for (int i = 0; i < 16; i++) {
                int idx = tid + i*128;
                int c = idx >> 6, n = idx & 63;
                int cg = k0 + c;
                const float* xp = (cg < csplit) ? Xaz + (size_t)cg*N
                                                : Xbz + (size_t)(cg-csplit)*N;
                bpre[i] = xp[j0 + n];
            }
        }
        /* compute: two k16 slices */
        #pragma unroll
        for (int s = 0; s < 2; s++) {
            int s8 = s*8;
            unsigned ah[2][4], al[2][4], bh[4][2], bl[4][2];
            #pragma unroll
            for (int mt = 0; mt < 2; mt++) {
                int r0 = wm*32 + mt*16 + g;
                ah[mt][0]=sAh[r0][s8+t];    al[mt][0]=sAl[r0][s8+t];
                ah[mt][1]=sAh[r0+8][s8+t];  al[mt][1]=sAl[r0+8][s8+t];
                ah[mt][2]=sAh[r0][s8+t+4];  al[mt][2]=sAl[r0][s8+t+4];
                ah[mt][3]=sAh[r0+8][s8+t+4];al[mt][3]=sAl[r0+8][s8+t+4];
            }
            #pragma unroll
            for (int nt = 0; nt < 4; nt++) {
                int cc = wn*32 + nt*8 + g;
                bh[nt][0]=sBh[s8+t][cc];   bl[nt][0]=sBl[s8+t][cc];
                bh[nt][1]=sBh[s8+t+4][cc]; bl[nt][1]=sBl[s8+t+4][cc];
            }
            #pragma unroll
            for (int mt = 0; mt < 2; mt++)
                #pragma unroll
                for (int nt = 0; nt < 4; nt++) {
                    mma16(acc[mt][nt], ah[mt], bh[nt]);
                    mma16(acc[mt][nt], ah[mt], bl[nt]);
                    mma16(acc[mt][nt], al[mt], bh[nt]);
                }
        }
    }
    /* epilogue */
    #pragma unroll
    for (int mt = 0; mt < 2; mt++) {
        #pragma unroll
        for (int nt = 0; nt < 4; nt++) {
            int row0 = o0 + wm*32 + mt*16 + g;
            int col0 = j0 + wn*32 + nt*8 + 2*t;
            #pragma unroll
            for (int e = 0; e < 4; e++) {
                int o  = row0 + (e >> 1)*8;
                int jj = col0 + (e & 1);
                float v = acc[mt][nt][e]*alpha + (bias ? bias[o] : 0.f);
                if (act == 2) v = v > 0.f ? v : (__expf(v) - 1.f);
                if (res) v += res[(size_t)z*(size_t)resz + (size_t)o*N + jj];
                Out[(size_t)z*(size_t)outz + (size_t)o*N + jj] = v;
            }
        }
    }
}

/* linear attention stage 1: partial KV[64][64] & ksum[64] per (chunk,h,b) */
__global__ void __launch_bounds__(256) attn_kv_kernel(
    const float* __restrict__ K, const float* __restrict__ V,
    float* __restrict__ part, int ns)
{
    int chunk = blockIdx.x, h = blockIdx.y, b = blockIdx.z;
    int mlen = ns / NCHUNK, m0 = chunk * mlen;
    const float* Kb = K + (size_t)b*DD*ns;
    const float* Vb = V + (size_t)b*DD*ns;
    __shared__ float ks[64][33];
    __shared__ float vs[64][33];
    int tid = threadIdx.x;
    int qi0 = (tid>>4)*4, ki0 = (tid&15)*4;
    float acc[4][4]={{0,0,0,0},{0,0,0,0},{0,0,0,0},{0,0,0,0}};
    float ksum = 0.f, invm = 1.f/(float)ns;
    for (int mt = 0; mt < mlen; mt += 32) {
        __syncthreads();
        for (int idx = tid; idx < 64*32; idx += 256) {
            int d = idx>>5, mm = idx&31, m = m0+mt+mm;
            float kr = Kb[(size_t)(d*4+h)*ns + m];
            ks[d][mm] = kr>0.f ? kr+1.f : __expf(kr);
            vs[d][mm] = Vb[(size_t)(d*4+h)*ns + m]*invm;
        }
        __syncthreads();
        if (tid < 64) {
            #pragma unroll
            for (int mm=0;mm<32;mm++) ksum += ks[tid][mm];
        }
        #pragma unroll 4
        for (int mm=0;mm<32;mm++){
            float vv[4], kv[4];
            #pragma unroll
            for (int i=0;i<4;i++) vv[i]=vs[qi0+i][mm];
            #pragma unroll
            for (int j=0;j<4;j++) kv[j]=ks[ki0+j][mm];
            #pragma unroll
            for (int i=0;i<4;i++)
                #pragma unroll
                for (int j=0;j<4;j++) acc[i][j]+=vv[i]*kv[j];
        }
    }
    float* dst = part + (size_t)chunk*KVSLOT;
    size_t base = (size_t)(b*4+h)*64;
    #pragma unroll
    for (int i=0;i<4;i++)
        #pragma unroll
        for (int j=0;j<4;j++)
            dst[(base+qi0+i)*64 + ki0+j] = acc[i][j];
    if (tid < 64) dst[32768 + base + tid] = ksum;
}

__global__ void kv_reduce_kernel(const float* __restrict__ part, float* __restrict__ o)
{
    int i = blockIdx.x*256 + threadIdx.x;
    if (i < KVSLOT) {
        float s = 0.f;
        #pragma unroll
        for (int c=0;c<NCHUNK;c++) s += part[(size_t)c*KVSLOT + i];
        o[i] = s;
    }
}

__global__ void __launch_bounds__(128) attn_out_kernel(
    const float* __restrict__ Q, const float* __restrict__ KVr,
    float* __restrict__ O_, int nq, int ns)
{
    int b = blockIdx.z, h = blockIdx.y;
    int m = blockIdx.x*128 + threadIdx.x;
    __shared__ float kvs[64][64];
    __shared__ float kss[64];
    const float* src = KVr + (size_t)(b*4+h)*4096;
    for (int i = threadIdx.x; i < 4096; i += 128) kvs[i>>6][i&63] = src[i];
    if (threadIdx.x < 64) kss[threadIdx.x] = KVr[32768 + (size_t)(b*4+h)*64 + threadIdx.x];
    __syncthreads();
    const float* Qb = Q + (size_t)b*DD*nq;
    float qv[64], denom = 0.f;
    #pragma unroll
    for (int d=0;d<64;d++){
        float q = Qb[(size_t)(d*4+h)*nq + m];
        q = q>0.f ? q+1.f : __expf(q);
        qv[d]=q; denom += q*kss[d];
    }
    float zf = (float)ns/(denom + 1e-6f);
    float* Ob = O_ + (size_t)b*DD*nq;
    for (int qd=0; qd<64; qd++){
        float accv = 0.f;
        #pragma unroll
        for (int d=0;d<64;d++) accv += qv[d]*kvs[qd][d];
        Ob[(size_t)(qd*4+h)*nq + m] = accv*zf;
    }
}

__global__ void __launch_bounds__(256) instnorm_relu_kernel(float* X, int C, int n)
{
    int c = blockIdx.x, b = blockIdx.y;
    float* row = X + ((size_t)b*C + c)*n;
    int tid = threadIdx.x;
    float s=0.f, s2=0.f;
    for (int i=tid;i<n;i+=256){ float v=row[i]; s+=v; s2+=v*v; }
    __shared__ float sm1[256], sm2[256];
    sm1[tid]=s; sm2[tid]=s2; __syncthreads();
    for (int st=128;st;st>>=1){
        if (tid<st){ sm1[tid]+=sm1[tid+st]; sm2[tid]+=sm2[tid+st]; }
        __syncthreads();
    }
    float mean = sm1[0]/(float)n;
    float var = sm2[0]/(float)n - mean*mean;
    float rstd = rsqrtf(var + 1e-5f);
    for (int i=tid;i<n;i+=256){
        float v = (row[i]-mean)*rstd;
        row[i] = v>0.f ? v : 0.f;
    }
}

__global__ void gat_vec_kernel(const float* __restrict__ gatW,
                               const float* __restrict__ gata, float* __restrict__ wa)
{
    int gg = blockIdx.x, d = threadIdx.x;
    const float* W = gatW + (size_t)gg*DD*DD;
    const float* a = gata + (size_t)gg*2*DD;
    float s1=0.f, s2=0.f;
    for (int o=0;o<DD;o++){ float w=W[(size_t)d*DD+o]; s1+=w*a[o]; s2+=w*a[DD+o]; }
    wa[gg*2*DD + d] = s1;
    wa[gg*2*DD + DD + d] = s2;
}

__global__ void __launch_bounds__(256) gat_agg_kernel(
    const float* __restrict__ d3, const float* __restrict__ d2d,
    const float* __restrict__ wa, float* __restrict__ agg, int n)
{
    int b = blockIdx.y;
    int warp = threadIdx.x>>5, lane = threadIdx.x&31;
    int nn = blockIdx.x*8 + warp;
    const float* Wa1 = wa;
    const float* Wa2 = wa + DD;
    const float* d3b = d3 + (size_t)b*DD*n;
    const float* d2b = d2d + (size_t)b*DD*(size_t)n*8;
    size_t n8 = (size_t)n*8;
    float x3[8], w2v[8];
    float sself=0.f, s0=0.f;
    #pragma unroll
    for (int r=0;r<8;r++){
        int d = lane + r*32;
        x3[r]=d3b[(size_t)d*n+nn]; w2v[r]=Wa2[d];
        sself += x3[r]*Wa1[d]; s0 += x3[r]*w2v[r];
    }
    #pragma unroll
    for (int off=16;off;off>>=1){
        sself += __shfl_xor_sync(0xffffffffu, sself, off);
        s0    += __shfl_xor_sync(0xffffffffu, s0, off);
    }
    float e[9]; e[0] = sself + s0;
    size_t nbase = (size_t)nn*8;
    #pragma unroll
    for (int l=1;l<9;l++){
        float sl = 0.f;
        #pragma unroll
        for (int r=0;r<8;r++)
            sl += d2b[(size_t)(lane+r*32)*n8 + nbase + (l-1)] * w2v[r];
        #pragma unroll
        for (int off=16;off;off>>=1) sl += __shfl_xor_sync(0xffffffffu, sl, off);
        e[l] = sself + sl;
    }
    float mx = -1e30f;
    #pragma unroll
    for (int l=0;l<9;l++){ e[l] = e[l]>0.f ? e[l] : 0.2f*e[l]; mx = fmaxf(mx, e[l]); }
    float sum = 0.f;
    #pragma unroll
    for (int l=0;l<9;l++){ e[l] = __expf(e[l]-mx); sum += e[l]; }
    float inv = 1.f/sum;
    float accv[8];
    #pragma unroll
    for (int r=0;r<8;r++) accv[r] = e[0]*inv*x3[r];
    #pragma unroll
    for (int l=1;l<9;l++){
        float al = e[l]*inv;
        #pragma unroll
        for (int r=0;r<8;r++)
            accv[r] += al * d2b[(size_t)(lane+r*32)*n8 + nbase + (l-1)];
    }
    float* ab = agg + (size_t)b*DD*n;
    #pragma unroll
    for (int r=0;r<8;r++) ab[(size_t)(lane+r*32)*n + nn] = accv[r];
}

__global__ void colnorm_kernel(float* X, int n)
{
    int b = blockIdx.y;
    int col = blockIdx.x*256 + threadIdx.x;
    float* Xb = X + (size_t)b*DD*n;
    float s = 0.f;
    for (int d=0;d<DD;d++){ float v=Xb[(size_t)d*n+col]; s += v*v; }
    float inv = 1.f / fmaxf(sqrtf(s), 1e-12f);
    for (int d=0;d<DD;d++) Xb[(size_t)d*n+col] *= inv;
}

__global__ void __launch_bounds__(256) row_stats_kernel(
    const float* __restrict__ S, float* rmax, float* rsum, int n1, int n2)
{
    int br = blockIdx.y*n1 + blockIdx.x;
    const float* row = S + (size_t)br*n2;
    int tid = threadIdx.x;
    __shared__ float sm[256];
    float mx = -1e30f;
    for (int j=tid;j<n2;j+=256) mx = fmaxf(mx, row[j]);
    sm[tid]=mx; __syncthreads();
    for (int st=128;st;st>>=1){ if (tid<st) sm[tid]=fmaxf(sm[tid],sm[tid+st]); __syncthreads(); }
    mx = sm[0]; __syncthreads();
    float s = 0.f;
    for (int j=tid;j<n2;j+=256) s += __expf(row[j]-mx);
    sm[tid]=s; __syncthreads();
    for (int st=128;st;st>>=1){ if (tid<st) sm[tid]+=sm[tid+st]; __syncthreads(); }
    if (tid==0){ rmax[br]=mx; rsum[br]=sm[0]; }
}

__global__ void col_stats_kernel(const float* __restrict__ S,
                                 float* cmax, float* csum, int n1, int n2)
{
    int b = blockIdx.y;
    int c = blockIdx.x*256 + threadIdx.x;
    const float* Sb = S + (size_t)b*n1*n2;
    float mx = -1e30f, s = 0.f;
    for (int r=0;r<n1;r++){
        float v = Sb[(size_t)r*n2 + c];
        if (v > mx){ s = s*__expf(mx-v) + 1.f; mx = v; }
        else s += __expf(v-mx);
    }
    cmax[b*n1 + c] = mx;
    csum[b*n1 + c] = s;
}

__global__ void conf_kernel(const float* __restrict__ S,
    const float* __restrict__ rmax, const float* __restrict__ rsum,
    const float* __restrict__ cmax, const float* __restrict__ csum,
    float* __restrict__ conf)
{
    size_t idx = (size_t)blockIdx.x*256 + threadIdx.x;
    int z = (int)(idx / ((size_t)NB*NB));
    size_t rem = idx - (size_t)z*NB*NB;
    int n = (int)(rem / NB), m = (int)(rem % NB);
    float s = S[idx];
    conf[idx] = __expf(2.f*s - rmax[z*NB+n] - cmax[z*NB+m])
                / (rsum[z*NB+n]*csum[z*NB+m]);
}

__global__ void __launch_bounds__(256) rowargmax_kernel(
    const float* __restrict__ conf0, int* i0, float* m0)
{
    int n = blockIdx.x;
    const float* row = conf0 + (size_t)n*NB;
    int tid = threadIdx.x;
    float best = -1e30f; int bidx = 0;
    for (int m=tid;m<NB;m+=256){ float v=row[m]; if (v>best){best=v;bidx=m;} }
    __shared__ float bv[256]; __shared__ int bi[256];
    bv[tid]=best; bi[tid]=bidx; __syncthreads();
    for (int st=128;st;st>>=1){
        if (tid<st){
            if (bv[tid+st]>bv[tid] || (bv[tid+st]==bv[tid] && bi[tid+st]<bi[tid])){
                bv[tid]=bv[tid+st]; bi[tid]=bi[tid+st];
            }
        }
        __syncthreads();
    }
    if (tid==0){ i0[n]=bi[0]; m0[n]=bv[0]; }
}

__global__ void colargmax_kernel(const float* __restrict__ conf0, int* i1, float* m1)
{
    int m = blockIdx.x*256 + threadIdx.x;
    float best = -1e30f; int bidx = 0;
    for (int n=0;n<NB;n++){
        float v = conf0[(size_t)n*NB + m];
        if (v > best){ best=v; bidx=n; }
    }
    i1[m]=bidx; m1[m]=best;
}

__global__ void match0_kernel(const int* i0, const int* i1, const float* m0,
                              float* out, float* ms0buf, int* valid0)
{
    int n = blockIdx.x*256 + threadIdx.x;
    int t = i0[n];
    int mutual = (i1[t] == n);
    float ms0 = mutual ? m0[n] : 0.f;
    int v0 = mutual && (ms0 > 0.2f);
    out[n] = v0 ? (float)t : -1.f;
    out[2*NB + n] = ms0;
    ms0buf[n] = ms0;
    valid0[n] = v0;
}

__global__ void match1_kernel(const int* i0, const int* i1,
                              const float* ms0buf, const int* valid0, float* out)
{
    int m = blockIdx.x*256 + threadIdx.x;
    int t = i1[m];
    int mutual = (i0[t] == m);
    float ms1 = mutual ? ms0buf[t] : 0.f;
    int v1 = mutual && valid0[t];
    out[NB + m] = v1 ? (float)t : -1.f;
    out[3*NB + m] = ms1;
}

/* --------------------------------- host ---------------------------------- */
static void* gsym(const void* s){ void* p=nullptr; cudaGetSymbolAddress(&p, s); return p; }

struct Ptrs {
    float *dq,*d3,*dqold,*qb,*kb,*vb,*ob,*msg,*agg,*tb,*sc,*kvpart,*kvred,*wa;
    float *rmax,*rsum,*cmax,*csum,*m0,*m1,*ms0buf;
    int *i0,*i1,*valid0;
};

static void ap(float* x, const float* src, int ai,
               const float* projw, const float* projb,
               const float* mergew, const float* mergeb,
               const float* mlp1w, const float* mlp1b,
               const float* mlp2w, const float* mlp2b, const Ptrs& P)
{
    const int N = NB;
    const long long DN = (long long)DD*N;
    dim3 g4(N/64, 4, 2), g8(N/64, 8, 2);
    const float* pw = projw + (size_t)ai*3*DD*DD;
    const float* pb = projb + (size_t)ai*3*DD;
    gemm_tc<<<g4,128>>>(pw,         0,0,DD, x,  DN, x,  DN, DD, pb,      nullptr,0, P.qb, DN, DD, N, 1.f, 0);
    gemm_tc<<<g4,128>>>(pw+DD*DD,   0,0,DD, src,DN, src,DN, DD, pb+DD,   nullptr,0, P.kb, DN, DD, N, 1.f, 0);
    gemm_tc<<<g4,128>>>(pw+2*DD*DD, 0,0,DD, src,DN, src,DN, DD, pb+2*DD, nullptr,0, P.vb, DN, DD, N, 1.f, 0);
    attn_kv_kernel<<<dim3(NCHUNK,4,2),256>>>(P.kb, P.vb, P.kvpart, N);
    kv_reduce_kernel<<<KVSLOT/256,256>>>(P.kvpart, P.kvred);
    attn_out_kernel<<<dim3(N/128,4,2),128>>>(P.qb, P.kvred, P.ob, N, N);
    gemm_tc<<<g4,128>>>(mergew+(size_t)ai*DD*DD, 0,0,DD, P.ob,DN, P.ob,DN, DD,
                        mergeb+(size_t)ai*DD, nullptr,0, P.msg, DN, DD, N, 1.f, 0);
    gemm_tc<<<g8,128>>>(mlp1w+(size_t)ai*512*512, 0,0,512, x,DN, P.msg,DN, DD,
                        mlp1b+(size_t)ai*512, nullptr,0, P.tb, 512LL*N, 512, N, 1.f, 0);
    instnorm_relu_kernel<<<dim3(512,2),256>>>(P.tb, 512, N);
    gemm_tc<<<g4,128>>>(mlp2w+(size_t)ai*DD*512, 0,0,DD, P.tb,512LL*N, P.tb,512LL*N, 512,
                        mlp2b+(size_t)ai*DD, x, DN, x, DN, 512, N, 1.f, 0);
}

extern "C" void kernel_launch(void* const* d_in, const int* in_sizes, int n_in,
                              void* d_out, int out_size)
{
    const float* in_dq   = (const float*)d_in[0];
    const float* in_d3   = (const float*)d_in[1];
    const float* in_d2db = (const float*)d_in[2];
    const float* projw   = (const float*)d_in[3];
    const float* projb   = (const float*)d_in[4];
    const float* mergew  = (const float*)d_in[5];
    const float* mergeb  = (const float*)d_in[6];
    const float* mlp1w   = (const float*)d_in[7];
    const float* mlp1b   = (const float*)d_in[8];
    const float* mlp2w   = (const float*)d_in[9];
    const float* mlp2b   = (const float*)d_in[10];
    const float* gatW    = (const float*)d_in[11];
    const float* gata    = (const float*)d_in[12];
    const float* finw    = (const float*)d_in[13];
    const float* finb    = (const float*)d_in[14];
    float* out = (float*)d_out;

    Ptrs P;
    P.dq=(float*)gsym(g_dq); P.d3=(float*)gsym(g_d3); P.dqold=(float*)gsym(g_dqold);
    P.qb=(float*)gsym(g_qb); P.kb=(float*)gsym(g_kb); P.vb=(float*)gsym(g_vb);
    P.ob=(float*)gsym(g_ob); P.msg=(float*)gsym(g_msg); P.agg=(float*)gsym(g_agg);
    P.tb=(float*)gsym(g_tb); P.sc=(float*)gsym(g_sc);
    P.kvpart=(float*)gsym(g_kvpart); P.kvred=(float*)gsym(g_kvred); P.wa=(float*)gsym(g_wa);
    P.rmax=(float*)gsym(g_rmax); P.rsum=(float*)gsym(g_rsum);
    P.cmax=(float*)gsym(g_cmax); P.csum=(float*)gsym(g_csum);
    P.m0=(float*)gsym(g_m0); P.m1=(float*)gsym(g_m1); P.ms0buf=(float*)gsym(g_ms0buf);
    P.i0=(int*)gsym(g_i0); P.i1=(int*)gsym(g_i1); P.valid0=(int*)gsym(g_valid0);

    const int N = NB;
    const long long DN = (long long)DD*N;
    size_t bytes = (size_t)2*DD*N*sizeof(float);
    cudaMemcpyAsync(P.dq, in_dq, bytes, cudaMemcpyDeviceToDevice);
    cudaMemcpyAsync(P.d3, in_d3, bytes, cudaMemcpyDeviceToDevice);
    gat_vec_kernel<<<4,256>>>(gatW, gata, P.wa);

    int gi = 0, ai = 0;
    for (int step = 0; step < 12; step++) {
        int t = step % 3;
        if (t == 0) {
            gat_agg_kernel<<<dim3(N/8,2),256>>>(P.d3, in_d2db, P.wa + gi*2*DD, P.agg, N);
            gemm_tc<<<dim3(N/64,4,2),128>>>(gatW+(size_t)gi*DD*DD, 0,1,DD,
                P.agg,DN, P.agg,DN, DD, nullptr, nullptr,0, P.d3, DN, DD, N, 1.f, 2);
            gi++;
        } else if (t == 1) {
            ap(P.dq, P.dq, ai, projw,projb,mergew,mergeb,mlp1w,mlp1b,mlp2w,mlp2b, P);
            ap(P.d3, P.d3, ai, projw,projb,mergew,mergeb,mlp1w,mlp1b,mlp2w,mlp2b, P);
            ai++;
        } else {
            cudaMemcpyAsync(P.dqold, P.dq, bytes, cudaMemcpyDeviceToDevice);
            ap(P.dq, P.d3,    ai, projw,projb,mergew,mergeb,mlp1w,mlp1b,mlp2w,mlp2b, P);
            ap(P.d3, P.dqold, ai, projw,projb,mergew,mergeb,mlp1w,mlp1b,mlp2w,mlp2b, P);
            ai++;
        }
    }

    gemm_tc<<<dim3(N/64,4,2),128>>>(finw, 0,0,DD, P.dq,DN, P.dq,DN, DD, finb,
                                    nullptr,0, P.qb, DN, DD, N, 1.f, 0);
    gemm_tc<<<dim3(N/64,4,2),128>>>(finw, 0,0,DD, P.d3,DN, P.d3,DN, DD, finb,
                                    nullptr,0, P.kb, DN, DD, N, 1.f, 0);
    colnorm_kernel<<<dim3(N/256,2),256>>>(P.qb, N);
    colnorm_kernel<<<dim3(N/256,2),256>>>(P.kb, N);

    /* scores: [b, n1, n2] = mq^T md / 0.1 */
    gemm_tc<<<dim3(N/64,N/64,2),128>>>(P.qb, DN, 1, N, P.kb, DN, P.kb, DN, DD,
                                       nullptr, nullptr,0, P.sc, (long long)N*N,
                                       DD, N, 10.f, 0);
    row_stats_kernel<<<dim3(N,2),256>>>(P.sc, P.rmax, P.rsum, N, N);
    col_stats_kernel<<<dim3(N/256,2),256>>>(P.sc, P.cmax, P.csum, N, N);

    float* conf = out + 4*NB;
    conf_kernel<<<(unsigned)((size_t)2*N*N/256),256>>>(P.sc, P.rmax, P.rsum,
                                                       P.cmax, P.csum, conf);
    rowargmax_kernel<<<N,256>>>(conf, P.i0, P.m0);
    colargmax_kernel<<<N/256,256>>>(conf, P.i1, P.m1);
    match0_kernel<<<N/256,256>>>(P.i0, P.i1, P.m0, out, P.ms0buf, P.valid0);
    match1_kernel<<<N/256,256>>>(P.i0, P.i1, P.ms0buf, P.valid0, out);
}